// round 7
// baseline (speedup 1.0000x reference)
#include <cuda_runtime.h>

// Problem constants
#define BB 16
#define NL 4097          // x0 rows per batch
#define NM 1024          // p_m rows
#define DS 256
#define DM 512
#define DL 1024
#define NKV 4098         // cls + NL
#define NCHUNK 64        // big covers 64*64 = 4096 rows; row 4096 handled in epi
#define MCH 32           // m-chunks for transposed gemv
#define GRID 148         // persistent-kernel grid (co-resident on 152 SMs)

// ---------------- device scratch ----------------
__device__ float g_csp  [BB*DM];
__device__ float g_q1   [BB*DM];
__device__ float g_qk1  [BB*DM];
__device__ float g_cmp  [BB*DL];
__device__ float g_q2   [BB*DL];
__device__ float g_qk2  [BB*DL];
__device__ float g_att1s[BB*(NM+1)];   // unnormalized exp(score/22)
__device__ float g_zinv [BB];
__device__ float g_a1p  [BB*NKV];
__device__ float g_PE   [BB*NCHUNK*DL];
__device__ float g_PA   [BB*NCHUNK*DL];
__device__ float g_PZ   [BB*NCHUNK];
__device__ float g_eps  [BB*3];        // ecls, wl2, zsh per batch
__device__ float g_u    [BB*DL];
__device__ float g_outv [BB*DL];
__device__ float g_gs   [BB*DS];
__device__ float g_part1[MCH*BB*DM];
__device__ float g_part2[MCH*BB*DL];
__device__ unsigned g_gbar[16];        // monotone grid-barrier counters (replay-safe)

// ---------------- grid barrier (monotone counter; never reset) ----------------
__device__ __forceinline__ void grid_barrier(int slot)
{
    __syncthreads();
    __threadfence();
    __syncthreads();
    if (threadIdx.x == 0) {
        unsigned arr = atomicAdd(&g_gbar[slot], 1u) + 1u;
        unsigned tgt = ((arr + GRID - 1u) / GRID) * GRID;
        while (*(volatile unsigned*)&g_gbar[slot] < tgt) { }
        __threadfence();
    }
    __syncthreads();
}

// ---------------- multi-batch GEMV task (no early return) ----------------
__device__ __forceinline__ void gemvA_task(int task, const float* __restrict__ W,
                                           const float* __restrict__ X, int ldx4,
                                           const float* __restrict__ bias,
                                           float* __restrict__ Y, int M, int D)
{
    int m = task * 8 + (threadIdx.x >> 5);
    int lane = threadIdx.x & 31;
    if (m < M) {
        const float4* w4 = (const float4*)(W + (size_t)m * D);
        const float4* x4 = (const float4*)X;
        int D4 = D >> 2;
        float acc[BB];
#pragma unroll
        for (int b = 0; b < BB; b++) acc[b] = 0.f;
        for (int f = lane; f < D4; f += 32) {
            float4 w = w4[f];
#pragma unroll
            for (int b = 0; b < BB; b++) {
                float4 x = x4[(size_t)b * ldx4 + f];
                acc[b] += w.x*x.x + w.y*x.y + w.z*x.z + w.w*x.w;
            }
        }
#pragma unroll
        for (int b = 0; b < BB; b++) {
            float v = acc[b];
#pragma unroll
            for (int o = 16; o; o >>= 1) v += __shfl_xor_sync(~0u, v, o);
            if (lane == 0) Y[(size_t)b * M + m] = v + (bias ? bias[m] : 0.f);
        }
    }
}

// ---------------- transposed GEMV partial task (uses smem scratch q) ----------------
__device__ __forceinline__ void gemvB_task(int dx, int my, const float* __restrict__ W,
                                           const float* __restrict__ X,
                                           float* __restrict__ part, int M, int D,
                                           float* q /* smem, >= BB*32 */)
{
    int d = dx * 256 + threadIdx.x;
    int rows = M / MCH;                 // 16 or 32
    int m0 = my * rows;
    for (int idx = threadIdx.x; idx < BB * rows; idx += 256) {
        int bb = idx / rows, mm = idx - bb * rows;
        q[bb * rows + mm] = X[(size_t)bb * M + m0 + mm];
    }
    __syncthreads();
    float acc[BB];
#pragma unroll
    for (int b = 0; b < BB; b++) acc[b] = 0.f;
    for (int mm = 0; mm < rows; mm++) {
        float w = W[(size_t)(m0 + mm) * D + d];
#pragma unroll
        for (int b = 0; b < BB; b++) acc[b] += w * q[b * rows + mm];
    }
#pragma unroll
    for (int b = 0; b < BB; b++)
        part[((size_t)my * BB + b) * D + d] = acc[b];
    __syncthreads();   // protect q before next task reuses it
}

__device__ __forceinline__ void gemvBred_task(int t, const float* __restrict__ part,
                                              float* __restrict__ Y, int D)
{
    int b = t / D, d = t - b * D;
    float acc = 0.f;
#pragma unroll
    for (int c = 0; c < MCH; c++) acc += part[((size_t)c * BB + b) * D + d];
    Y[t] = acc;
}

// ================= prep: entire pre-big chain in one kernel =================
__global__ __launch_bounds__(256) void prep_kernel(
    const float* __restrict__ x1,     const float* __restrict__ x2,
    const float* __restrict__ f_s_w,  const float* __restrict__ f_s_b,
    const float* __restrict__ f_m_w,  const float* __restrict__ f_m_b,
    const float* __restrict__ Wq1,    const float* __restrict__ Wk1,
    const float* __restrict__ Wq2,    const float* __restrict__ Wk2,
    const float* __restrict__ proj_w, const float* __restrict__ proj_b)
{
    extern __shared__ float sm[];      // 65600 B: q scratch (P2) / att (P6)
    int bid = blockIdx.x, tid = threadIdx.x;
    int warp = tid >> 5, lane = tid & 31;

    // P0: csp (64 tasks) + cmp (128 tasks)
    for (int task = bid; task < 192; task += GRID) {
        if (task < 64)
            gemvA_task(task, f_s_w, x2, (NL * DS) / 4, f_s_b, g_csp, DM, DS);
        else
            gemvA_task(task - 64, f_m_w, x1, ((NM + 1) * DM) / 4, f_m_b, g_cmp, DL, DM);
    }
    grid_barrier(0);

    // P1: q1 (64) + q2 (128)
    for (int task = bid; task < 192; task += GRID) {
        if (task < 64)
            gemvA_task(task, Wq1, g_csp, DM / 4, nullptr, g_q1, DM, DM);
        else
            gemvA_task(task - 64, Wq2, g_cmp, DL / 4, nullptr, g_q2, DL, DL);
    }
    grid_barrier(1);

    // P2: qk1 partials (64) + qk2 partials (128)
    for (int task = bid; task < 192; task += GRID) {
        if (task < 64)
            gemvB_task(task & 1, task >> 1, Wk1, g_q1, g_part1, DM, DM, sm);
        else {
            int id = task - 64;
            gemvB_task(id & 3, id >> 2, Wk2, g_q2, g_part2, DL, DL, sm);
        }
    }
    grid_barrier(2);

    // P3: reduce qk1 (32) + qk2 (64)
    for (int task = bid; task < 96; task += GRID) {
        if (task < 32)
            gemvBred_task(task * 256 + tid, g_part1, g_qk1, DM);
        else
            gemvBred_task((task - 32) * 256 + tid, g_part2, g_qk2, DL);
    }
    grid_barrier(3);

    // P4: att1 scores -> unnormalized exp (4096 four-row warp tasks + 16 cls tasks)
    {
        int gw = bid * 8 + warp;
        for (int task = gw; task < 4096 + 16; task += GRID * 8) {
            if (task < 4096) {
                int rr = task * 4;
                int b = rr >> 10, k0 = rr & 1023;
                const float4* qk = (const float4*)(g_qk1 + (size_t)b * DM);
                float4 q[4];
#pragma unroll
                for (int j = 0; j < 4; j++) q[j] = qk[lane + 32 * j];
#pragma unroll
                for (int i = 0; i < 4; i++) {
                    const float4* row = (const float4*)(x1 + ((size_t)b * (NM + 1) + 1 + k0 + i) * DM);
                    float s = 0.f;
#pragma unroll
                    for (int j = 0; j < 4; j++) {
                        float4 v = __ldcs(row + lane + 32 * j);
                        s += v.x*q[j].x + v.y*q[j].y + v.z*q[j].z + v.w*q[j].w;
                    }
#pragma unroll
                    for (int o = 16; o; o >>= 1) s += __shfl_xor_sync(~0u, s, o);
                    if (!lane) g_att1s[(size_t)b * (NM + 1) + 1 + k0 + i] = __expf(s * (1.f / 22.f));
                }
            } else {
                int b = task - 4096;
                float p = 0.f;
                for (int i = lane; i < DM; i += 32) p += g_csp[b * DM + i] * g_qk1[b * DM + i];
#pragma unroll
                for (int o = 16; o; o >>= 1) p += __shfl_xor_sync(~0u, p, o);
                if (!lane) g_att1s[(size_t)b * (NM + 1)] = __expf(p * (1.f / 22.f));
            }
        }
    }
    grid_barrier(4);

    // P5: per-batch Z (16 warp tasks)
    {
        int gw = bid * 8 + warp;
        if (gw < BB) {
            float z = 0.f;
            for (int i = lane; i < NM + 1; i += 32) z += g_att1s[(size_t)gw * (NM + 1) + i];
#pragma unroll
            for (int o = 16; o; o >>= 1) z += __shfl_xor_sync(~0u, z, o);
            if (!lane) g_zinv[gw] = 1.f / z;
        }
    }
    grid_barrier(5);

    // P6: projection with 1/Z folded in (513 j-groups of 8)
    {
        for (int idx = tid; idx < BB * (NM + 1); idx += 256) {
            int bb = idx / (NM + 1), i = idx - bb * (NM + 1);
            sm[idx] = g_att1s[(size_t)bb * (NM + 1) + i];
        }
        float zv[BB];
#pragma unroll
        for (int bb = 0; bb < BB; bb++) zv[bb] = g_zinv[bb];
        __syncthreads();
        for (int jt = bid; jt < 513; jt += GRID) {
            int j = jt * 8 + warp;
            if (j < NKV) {
                const float* wrow = proj_w + (size_t)j * (NM + 1);
                float acc[BB];
#pragma unroll
                for (int bb = 0; bb < BB; bb++) acc[bb] = 0.f;
                for (int i = lane; i < NM + 1; i += 32) {
                    float w = __ldcs(wrow + i);
#pragma unroll
                    for (int bb = 0; bb < BB; bb++) acc[bb] += w * sm[bb * (NM + 1) + i];
                }
#pragma unroll
                for (int bb = 0; bb < BB; bb++) {
                    float v = acc[bb];
#pragma unroll
                    for (int o = 16; o; o >>= 1) v += __shfl_xor_sync(~0u, v, o);
                    if (!lane) g_a1p[(size_t)bb * NKV + j] = v * zv[bb] + proj_b[j];
                }
            }
        }
    }
}

// ================= big: fused x0 pass (unchanged from R6) =================
__global__ __launch_bounds__(256) void big_kernel(const float* __restrict__ x0)
{
    int b = blockIdx.y, chunk = blockIdx.x;
    int t = threadIdx.x, warp = t >> 5, lane = t & 31;
    __shared__ float4 qk2s[256];
    __shared__ float4 Es[256], As[256];
    __shared__ float Zs[8];
    qk2s[t] = ((const float4*)(g_qk2 + (size_t)b * DL))[t];
    Es[t] = make_float4(0.f, 0.f, 0.f, 0.f);
    As[t] = make_float4(0.f, 0.f, 0.f, 0.f);
    __syncthreads();

    float4 aE[8], aA[8];
#pragma unroll
    for (int j = 0; j < 8; j++) { aE[j] = make_float4(0,0,0,0); aA[j] = make_float4(0,0,0,0); }
    float zacc = 0.f;
    int k0 = chunk * 64 + warp;
#pragma unroll 2
    for (int rr = 0; rr < 8; rr++) {
        int k = k0 + rr * 8;
        const float4* row = (const float4*)(x0 + ((size_t)b * NL + k) * DL);
        float4 v[8];
#pragma unroll
        for (int j = 0; j < 8; j++) v[j] = __ldcs(row + lane + 32 * j);
        float s = 0.f;
#pragma unroll
        for (int j = 0; j < 8; j++) {
            float4 q = qk2s[lane + 32 * j];
            s += v[j].x*q.x + v[j].y*q.y + v[j].z*q.z + v[j].w*q.w;
        }
#pragma unroll
        for (int o = 16; o; o >>= 1) s += __shfl_xor_sync(~0u, s, o);
        float w2 = __expf(s * (1.f / 32.f));
        float w1 = g_a1p[(size_t)b * NKV + k + 1];
        zacc += w2;
#pragma unroll
        for (int j = 0; j < 8; j++) {
            aE[j].x += w2 * v[j].x; aE[j].y += w2 * v[j].y; aE[j].z += w2 * v[j].z; aE[j].w += w2 * v[j].w;
            aA[j].x += w1 * v[j].x; aA[j].y += w1 * v[j].y; aA[j].z += w1 * v[j].z; aA[j].w += w1 * v[j].w;
        }
    }
    for (int w = 0; w < 8; w++) {
        if (warp == w) {
#pragma unroll
            for (int j = 0; j < 8; j++) {
                int idx = lane + 32 * j;
                float4 e = Es[idx];
                e.x += aE[j].x; e.y += aE[j].y; e.z += aE[j].z; e.w += aE[j].w;
                Es[idx] = e;
                float4 a = As[idx];
                a.x += aA[j].x; a.y += aA[j].y; a.z += aA[j].z; a.w += aA[j].w;
                As[idx] = a;
            }
            if (lane == 0) Zs[w] = zacc;
        }
        __syncthreads();
    }
    ((float4*)(g_PE + ((size_t)b * NCHUNK + chunk) * DL))[t] = Es[t];
    ((float4*)(g_PA + ((size_t)b * NCHUNK + chunk) * DL))[t] = As[t];
    if (t == 0) {
        float z = 0.f;
#pragma unroll
        for (int w = 0; w < 8; w++) z += Zs[w];
        g_PZ[b * NCHUNK + chunk] = z;
    }
}

// ================= epi: u + Wv + gs + broadcast in one kernel =================
__global__ __launch_bounds__(256) void epi_kernel(
    const float* __restrict__ x0, const float* __restrict__ Wv,
    const float* __restrict__ gs_w, const float* __restrict__ gs_b,
    float* __restrict__ out)
{
    __shared__ float red[256];
    int bid = blockIdx.x, tid = threadIdx.x;

    // P0: per-batch scalars (blocks 0..15)
    if (bid < BB) {
        int b = bid;
        float4 c4 = ((const float4*)(g_cmp + (size_t)b * DL))[tid];
        float4 q4 = ((const float4*)(g_qk2 + (size_t)b * DL))[tid];
        float4 x4 = ((const float4*)(x0 + ((size_t)b * NL + NL - 1) * DL))[tid];
        float p1 = c4.x*q4.x + c4.y*q4.y + c4.z*q4.z + c4.w*q4.w;
        float p2 = x4.x*q4.x + x4.y*q4.y + x4.z*q4.z + x4.w*q4.w;
        red[tid] = p1; __syncthreads();
        for (int s = 128; s; s >>= 1) { if (tid < s) red[tid] += red[tid + s]; __syncthreads(); }
        float d1 = red[0]; __syncthreads();
        red[tid] = p2; __syncthreads();
        for (int s = 128; s; s >>= 1) { if (tid < s) red[tid] += red[tid + s]; __syncthreads(); }
        float d2 = red[0]; __syncthreads();
        red[tid] = (tid < NCHUNK) ? g_PZ[b * NCHUNK + tid] : 0.f; __syncthreads();
        for (int s = 128; s; s >>= 1) { if (tid < s) red[tid] += red[tid + s]; __syncthreads(); }
        if (tid == 0) {
            float ecls = __expf(d1 * (1.f / 32.f));
            float wl2  = __expf(d2 * (1.f / 32.f));
            g_eps[b * 3 + 0] = ecls;
            g_eps[b * 3 + 1] = wl2;
            g_eps[b * 3 + 2] = ecls + wl2 + red[0];
        }
    }
    grid_barrier(8);

    // P1: u[b,d]
    for (int e = bid * 256 + tid; e < BB * DL; e += GRID * 256) {
        int b = e >> 10, d = e & 1023;
        float cmp = g_cmp[e];
        float xlast = x0[((size_t)b * NL + NL - 1) * DL + d];
        float ecls = g_eps[b * 3 + 0], wl2 = g_eps[b * 3 + 1], zsh = g_eps[b * 3 + 2];
        float esum = 0.f, asum = 0.f;
#pragma unroll 4
        for (int c = 0; c < NCHUNK; c++) {
            esum += g_PE[((size_t)b * NCHUNK + c) * DL + d];
            asum += g_PA[((size_t)b * NCHUNK + c) * DL + d];
        }
        float a1p0 = g_a1p[(size_t)b * NKV];
        float a1pl = g_a1p[(size_t)b * NKV + NKV - 1];
        esum += wl2 * xlast;
        asum += a1pl * xlast;
        g_u[e] = 0.3f * (a1p0 * cmp + asum) + 0.7f * (ecls * cmp + esum) / zsh;
    }
    grid_barrier(9);

    // P2: outv = Wv · u (128 tasks)
    for (int task = bid; task < 128; task += GRID)
        gemvA_task(task, Wv, g_u, DL / 4, nullptr, g_outv, DL, DL);
    grid_barrier(10);

    // P3: gs = gs_w · outv + gs_b (32 tasks)
    for (int task = bid; task < 32; task += GRID)
        gemvA_task(task, gs_w, g_outv, DL / 4, gs_b, g_gs, DS, DL);
    grid_barrier(11);

    // P4: broadcast g_s to all 4097 rows (2064 tasks)
    {
        int g = tid >> 6, l = tid & 63;
        for (int task = bid; task < BB * 129; task += GRID) {
            int b = task / 129, grp = task - b * 129;
            float4 val = ((const float4*)(g_gs + b * DS))[l];
            float4* ob = (float4*)out + (size_t)b * NL * 64;
            int base = grp * 32;
            int lim = base + 32; if (lim > NL) lim = NL;
            for (int r = base + g; r < lim; r += 4)
                __stcs(ob + (size_t)r * 64 + l, val);
        }
    }
}

// ---------------- launch: 3 graph nodes ----------------
extern "C" void kernel_launch(void* const* d_in, const int* in_sizes, int n_in,
                              void* d_out, int out_size)
{
    const float* x0     = (const float*)d_in[0];
    const float* x1     = (const float*)d_in[1];
    const float* x2     = (const float*)d_in[2];
    const float* f_s_w  = (const float*)d_in[3];
    const float* f_s_b  = (const float*)d_in[4];
    const float* f_m_w  = (const float*)d_in[5];
    const float* f_m_b  = (const float*)d_in[6];
    const float* Wq1    = (const float*)d_in[7];
    const float* Wk1    = (const float*)d_in[8];
    const float* Wq2    = (const float*)d_in[9];
    const float* Wk2    = (const float*)d_in[10];
    const float* Wv     = (const float*)d_in[11];
    const float* proj_w = (const float*)d_in[12];
    const float* proj_b = (const float*)d_in[13];
    const float* gs_w   = (const float*)d_in[14];
    const float* gs_b   = (const float*)d_in[15];

    static int init = 0;
    if (!init) {
        cudaFuncSetAttribute(prep_kernel, cudaFuncAttributeMaxDynamicSharedMemorySize,
                             BB * (NM + 1) * 4);
        init = 1;
    }

    prep_kernel<<<GRID, 256, BB * (NM + 1) * 4>>>(
        x1, x2, f_s_w, f_s_b, f_m_w, f_m_b, Wq1, Wk1, Wq2, Wk2, proj_w, proj_b);
    big_kernel<<<dim3(NCHUNK, BB), 256>>>(x0);
    epi_kernel<<<GRID, 256>>>(x0, Wv, gs_w, gs_b, (float*)d_out);
}

// round 9
// speedup vs baseline: 1.2647x; 1.2647x over previous
#include <cuda_runtime.h>

// Problem constants
#define BB 16
#define NL 4097          // x0 rows per batch
#define NM 1024          // p_m rows
#define DS 256
#define DM 512
#define DL 1024
#define NKV 4098         // cls + NL
#define NCHUNK 64        // big covers 64*64 = 4096 rows; row 4096 handled in tail
#define MCH 32           // m-chunks for transposed gemv
#define TGRID 148        // tail persistent grid (co-resident)

// ---------------- device scratch ----------------
__device__ float g_csp  [BB*DM];
__device__ float g_q1   [BB*DM];
__device__ float g_qk1  [BB*DM];
__device__ float g_cmp  [BB*DL];
__device__ float g_q2   [BB*DL];
__device__ float g_qk2  [BB*DL];
__device__ float g_att1s[BB*(NM+1)];   // unnormalized exp(score/22)
__device__ float g_a1p  [BB*NKV];
__device__ float g_PE   [BB*NCHUNK*DL];
__device__ float g_PA   [BB*NCHUNK*DL];
__device__ float g_PZ   [BB*NCHUNK];
__device__ float g_eps  [BB*3];        // ecls, wl2, zsh per batch
__device__ float g_u    [BB*DL];
__device__ float g_outv [BB*DL];
__device__ float g_gs   [BB*DS];
__device__ float g_part1[MCH*BB*DM];
__device__ float g_part2[MCH*BB*DL];
__device__ unsigned g_gbar[8];         // monotone grid-barrier counters (replay-safe)

// ---------------- grid barrier (monotone counter; never reset) ----------------
__device__ __forceinline__ void grid_barrier(int slot)
{
    __syncthreads();
    __threadfence();
    __syncthreads();
    if (threadIdx.x == 0) {
        unsigned arr = atomicAdd(&g_gbar[slot], 1u) + 1u;
        unsigned tgt = ((arr + TGRID - 1u) / TGRID) * TGRID;
        while (*(volatile unsigned*)&g_gbar[slot] < tgt) { }
        __threadfence();
    }
    __syncthreads();
}

// ---------------- multi-batch GEMV: Y[b,m] = bias[m] + W[m,:]·X[b,:] ----------------
__device__ __forceinline__ void gemvA_body(int mblk, const float* __restrict__ W,
                                           const float* __restrict__ X, int ldx4,
                                           const float* __restrict__ bias,
                                           float* __restrict__ Y, int M, int D)
{
    int m = mblk * 8 + (threadIdx.x >> 5);
    int lane = threadIdx.x & 31;
    if (m >= M) return;
    const float4* w4 = (const float4*)(W + (size_t)m * D);
    const float4* x4 = (const float4*)X;
    int D4 = D >> 2;
    float acc[BB];
#pragma unroll
    for (int b = 0; b < BB; b++) acc[b] = 0.f;
    for (int f = lane; f < D4; f += 32) {
        float4 w = w4[f];
#pragma unroll
        for (int b = 0; b < BB; b++) {
            float4 x = x4[(size_t)b * ldx4 + f];
            acc[b] += w.x*x.x + w.y*x.y + w.z*x.z + w.w*x.w;
        }
    }
#pragma unroll
    for (int b = 0; b < BB; b++) {
        float v = acc[b];
#pragma unroll
        for (int o = 16; o; o >>= 1) v += __shfl_xor_sync(~0u, v, o);
        if (lane == 0) Y[(size_t)b * M + m] = v + (bias ? bias[m] : 0.f);
    }
}

__global__ __launch_bounds__(256) void gemvA_kernel(
    const float* __restrict__ W, const float* __restrict__ X, int ldx4,
    const float* __restrict__ bias, float* __restrict__ Y, int M, int D)
{
    gemvA_body(blockIdx.x, W, X, ldx4, bias, Y, M, D);
}

// ---------------- transposed GEMV partials ----------------
__global__ __launch_bounds__(256) void gemvB_kernel(
    const float* __restrict__ W, const float* __restrict__ X,
    float* __restrict__ part, int M, int D)
{
    int d = blockIdx.x * 256 + threadIdx.x;
    int rows = M / MCH;                 // 16 or 32
    int m0 = blockIdx.y * rows;
    __shared__ float q[BB * 32];
    for (int idx = threadIdx.x; idx < BB * rows; idx += 256) {
        int bb = idx / rows, mm = idx - bb * rows;
        q[bb * rows + mm] = X[(size_t)bb * M + m0 + mm];
    }
    __syncthreads();
    float acc[BB];
#pragma unroll
    for (int b = 0; b < BB; b++) acc[b] = 0.f;
    for (int mm = 0; mm < rows; mm++) {
        float w = W[(size_t)(m0 + mm) * D + d];
#pragma unroll
        for (int b = 0; b < BB; b++) acc[b] += w * q[b * rows + mm];
    }
#pragma unroll
    for (int b = 0; b < BB; b++)
        part[((size_t)blockIdx.y * BB + b) * D + d] = acc[b];
}

__global__ __launch_bounds__(256) void gemvBred_kernel(
    const float* __restrict__ part, float* __restrict__ Y, int D)
{
    int t = blockIdx.x * 256 + threadIdx.x;
    int b = t / D, d = t - b * D;
    float acc = 0.f;
#pragma unroll
    for (int c = 0; c < MCH; c++) acc += part[((size_t)c * BB + b) * D + d];
    Y[t] = acc;
}

// ---------------- score1e: p_m scores -> unnormalized exp; blocks >= 512 do cls ----------------
__global__ __launch_bounds__(256) void score1e_kernel(const float* __restrict__ x1)
{
    int blk = blockIdx.x;
    int warp = threadIdx.x >> 5, lane = threadIdx.x & 31;
    if (blk < 512) {
        int gw = blk * 8 + warp;
        int rr = gw * 4;
        int b = rr >> 10, k0 = rr & 1023;
        const float4* qk = (const float4*)(g_qk1 + (size_t)b * DM);
        float4 q[4];
#pragma unroll
        for (int j = 0; j < 4; j++) q[j] = qk[lane + 32 * j];
#pragma unroll
        for (int i = 0; i < 4; i++) {
            const float4* row = (const float4*)(x1 + ((size_t)b * (NM + 1) + 1 + k0 + i) * DM);
            float s = 0.f;
#pragma unroll
            for (int j = 0; j < 4; j++) {
                float4 v = __ldcs(row + lane + 32 * j);
                s += v.x*q[j].x + v.y*q[j].y + v.z*q[j].z + v.w*q[j].w;
            }
#pragma unroll
            for (int o = 16; o; o >>= 1) s += __shfl_xor_sync(~0u, s, o);
            if (!lane) g_att1s[(size_t)b * (NM + 1) + 1 + k0 + i] = __expf(s * (1.f / 22.f));
        }
    } else {
        int b = (blk - 512) * 8 + warp;   // blocks 512,513 -> batches 0..15
        const float4* c4 = (const float4*)(g_csp + (size_t)b * DM);
        const float4* q4 = (const float4*)(g_qk1 + (size_t)b * DM);
        float p = 0.f;
#pragma unroll
        for (int j = 0; j < 4; j++) {
            float4 cc = c4[lane + 32 * j];
            float4 qq = q4[lane + 32 * j];
            p += cc.x*qq.x + cc.y*qq.y + cc.z*qq.z + cc.w*qq.w;
        }
#pragma unroll
        for (int o = 16; o; o >>= 1) p += __shfl_xor_sync(~0u, p, o);
        if (!lane) g_att1s[(size_t)b * (NM + 1)] = __expf(p * (1.f / 22.f));
    }
}

// ---------------- projZ: inline 1/Z + projection, all 16 batches per block ----------------
__global__ __launch_bounds__(256) void projZ_kernel(
    const float* __restrict__ proj_w, const float* __restrict__ proj_b)
{
    extern __shared__ float sm[];           // att [BB*(NM+1)] then zinv[16]
    float* att = sm;
    float* zs  = sm + BB * (NM + 1);
    int warp = threadIdx.x >> 5, lane = threadIdx.x & 31;
    for (int idx = threadIdx.x; idx < BB * (NM + 1); idx += 256) {
        int bb = idx / (NM + 1), i = idx - bb * (NM + 1);
        att[idx] = g_att1s[(size_t)bb * (NM + 1) + i];
    }
    __syncthreads();
#pragma unroll
    for (int h = 0; h < 2; h++) {           // warp w -> batches w, w+8 (deterministic)
        int bb = warp + 8 * h;
        float z = 0.f;
        for (int i = lane; i < NM + 1; i += 32) z += att[bb * (NM + 1) + i];
#pragma unroll
        for (int o = 16; o; o >>= 1) z += __shfl_xor_sync(~0u, z, o);
        if (!lane) zs[bb] = 1.f / z;
    }
    __syncthreads();
    int j = blockIdx.x * 8 + warp;
    if (j >= NKV) return;
    const float* wrow = proj_w + (size_t)j * (NM + 1);
    float acc[BB];
#pragma unroll
    for (int bb = 0; bb < BB; bb++) acc[bb] = 0.f;
    for (int i = lane; i < NM + 1; i += 32) {
        float w = __ldcs(wrow + i);
#pragma unroll
        for (int bb = 0; bb < BB; bb++) acc[bb] += w * att[bb * (NM + 1) + i];
    }
#pragma unroll
    for (int bb = 0; bb < BB; bb++) {
        float v = acc[bb];
#pragma unroll
        for (int o = 16; o; o >>= 1) v += __shfl_xor_sync(~0u, v, o);
        if (!lane) g_a1p[(size_t)bb * NKV + j] = v * zs[bb] + proj_b[j];
    }
}

// ---------------- big: fused x0 pass (proven) ----------------
__global__ __launch_bounds__(256) void big_kernel(const float* __restrict__ x0)
{
    int b = blockIdx.y, chunk = blockIdx.x;
    int t = threadIdx.x, warp = t >> 5, lane = t & 31;
    __shared__ float4 qk2s[256];
    __shared__ float4 Es[256], As[256];
    __shared__ float Zs[8];
    qk2s[t] = ((const float4*)(g_qk2 + (size_t)b * DL))[t];
    Es[t] = make_float4(0.f, 0.f, 0.f, 0.f);
    As[t] = make_float4(0.f, 0.f, 0.f, 0.f);
    __syncthreads();

    float4 aE[8], aA[8];
#pragma unroll
    for (int j = 0; j < 8; j++) { aE[j] = make_float4(0,0,0,0); aA[j] = make_float4(0,0,0,0); }
    float zacc = 0.f;
    int k0 = chunk * 64 + warp;
#pragma unroll 2
    for (int rr = 0; rr < 8; rr++) {
        int k = k0 + rr * 8;
        const float4* row = (const float4*)(x0 + ((size_t)b * NL + k) * DL);
        float4 v[8];
#pragma unroll
        for (int j = 0; j < 8; j++) v[j] = __ldcs(row + lane + 32 * j);
        float s = 0.f;
#pragma unroll
        for (int j = 0; j < 8; j++) {
            float4 q = qk2s[lane + 32 * j];
            s += v[j].x*q.x + v[j].y*q.y + v[j].z*q.z + v[j].w*q.w;
        }
#pragma unroll
        for (int o = 16; o; o >>= 1) s += __shfl_xor_sync(~0u, s, o);
        float w2 = __expf(s * (1.f / 32.f));
        float w1 = g_a1p[(size_t)b * NKV + k + 1];
        zacc += w2;
#pragma unroll
        for (int j = 0; j < 8; j++) {
            aE[j].x += w2 * v[j].x; aE[j].y += w2 * v[j].y; aE[j].z += w2 * v[j].z; aE[j].w += w2 * v[j].w;
            aA[j].x += w1 * v[j].x; aA[j].y += w1 * v[j].y; aA[j].z += w1 * v[j].z; aA[j].w += w1 * v[j].w;
        }
    }
    for (int w = 0; w < 8; w++) {
        if (warp == w) {
#pragma unroll
            for (int j = 0; j < 8; j++) {
                int idx = lane + 32 * j;
                float4 e = Es[idx];
                e.x += aE[j].x; e.y += aE[j].y; e.z += aE[j].z; e.w += aE[j].w;
                Es[idx] = e;
                float4 a = As[idx];
                a.x += aA[j].x; a.y += aA[j].y; a.z += aA[j].z; a.w += aA[j].w;
                As[idx] = a;
            }
            if (lane == 0) Zs[w] = zacc;
        }
        __syncthreads();
    }
    ((float4*)(g_PE + ((size_t)b * NCHUNK + chunk) * DL))[t] = Es[t];
    ((float4*)(g_PA + ((size_t)b * NCHUNK + chunk) * DL))[t] = As[t];
    if (t == 0) {
        float z = 0.f;
#pragma unroll
        for (int w = 0; w < 8; w++) z += Zs[w];
        g_PZ[b * NCHUNK + chunk] = z;
    }
}

// ---------------- tail: scalars -> u -> Wv·u -> gs -> broadcast, one node ----------------
__global__ __launch_bounds__(256) void tail_kernel(
    const float* __restrict__ x0, const float* __restrict__ Wv,
    const float* __restrict__ gs_w, const float* __restrict__ gs_b,
    float* __restrict__ out)
{
    __shared__ float red[256];
    int bid = blockIdx.x, tid = threadIdx.x;

    // P0: per-batch scalars (blocks 0..15)
    if (bid < BB) {
        int b = bid;
        float p1 = 0.f, p2 = 0.f;
#pragma unroll
        for (int i = 0; i < 4; i++) {
            int d = tid + 256 * i;
            float qk = g_qk2[b * DL + d];
            p1 += g_cmp[b * DL + d] * qk;
            p2 += x0[((size_t)b * NL + NL - 1) * DL + d] * qk;
        }
        red[tid] = p1; __syncthreads();
        for (int s = 128; s; s >>= 1) { if (tid < s) red[tid] += red[tid + s]; __syncthreads(); }
        float d1 = red[0]; __syncthreads();
        red[tid] = p2; __syncthreads();
        for (int s = 128; s; s >>= 1) { if (tid < s) red[tid] += red[tid + s]; __syncthreads(); }
        float d2 = red[0]; __syncthreads();
        red[tid] = (tid < NCHUNK) ? g_PZ[b * NCHUNK + tid] : 0.f; __syncthreads();
        for (int s = 128; s; s >>= 1) { if (tid < s) red[tid] += red[tid + s]; __syncthreads(); }
        if (tid == 0) {
            float ecls = __expf(d1 * (1.f / 32.f));
            float wl2  = __expf(d2 * (1.f / 32.f));
            g_eps[b * 3 + 0] = ecls;
            g_eps[b * 3 + 1] = wl2;
            g_eps[b * 3 + 2] = ecls + wl2 + red[0];
        }
    }
    grid_barrier(0);

    // P1: u[b,d]  (16384 elements)
    for (int e = bid * 256 + tid; e < BB * DL; e += TGRID * 256) {
        int b = e >> 10, d = e & 1023;
        float cmp = g_cmp[e];
        float xlast = x0[((size_t)b * NL + NL - 1) * DL + d];
        float ecls = g_eps[b * 3 + 0], wl2 = g_eps[b * 3 + 1], zsh = g_eps[b * 3 + 2];
        float esum = 0.f, asum = 0.f;
#pragma unroll 4
        for (int c = 0; c < NCHUNK; c++) {
            esum += g_PE[((size_t)b * NCHUNK + c) * DL + d];
            asum += g_PA[((size_t)b * NCHUNK + c) * DL + d];
        }
        float a1p0 = g_a1p[(size_t)b * NKV];
        float a1pl = g_a1p[(size_t)b * NKV + NKV - 1];
        esum += wl2 * xlast;
        asum += a1pl * xlast;
        g_u[e] = 0.3f * (a1p0 * cmp + asum) + 0.7f * (ecls * cmp + esum) / zsh;
    }
    grid_barrier(1);

    // P2: outv = Wv · u (128 tasks)
    for (int task = bid; task < 128; task += TGRID)
        gemvA_body(task, Wv, g_u, DL / 4, nullptr, g_outv, DL, DL);
    grid_barrier(2);

    // P3: gs = gs_w · outv + gs_b (32 tasks)
    for (int task = bid; task < 32; task += TGRID)
        gemvA_body(task, gs_w, g_outv, DL / 4, gs_b, g_gs, DS, DL);
    grid_barrier(3);

    // P4: broadcast gs to all 4097 rows (2064 tasks)
    {
        int g = tid >> 6, l = tid & 63;
        for (int task = bid; task < BB * 129; task += TGRID) {
            int b = task / 129, grp = task - b * 129;
            float4 val = ((const float4*)(g_gs + b * DS))[l];
            float4* ob = (float4*)out + (size_t)b * NL * 64;
            int base = grp * 32;
            int lim = base + 32; if (lim > NL) lim = NL;
            for (int r = base + g; r < lim; r += 4)
                __stcs(ob + (size_t)r * 64 + l, val);
        }
    }
}

// ---------------- launch: R6 fork-join topology, shorter chains ----------------
extern "C" void kernel_launch(void* const* d_in, const int* in_sizes, int n_in,
                              void* d_out, int out_size)
{
    const float* x0     = (const float*)d_in[0];
    const float* x1     = (const float*)d_in[1];
    const float* x2     = (const float*)d_in[2];
    const float* f_s_w  = (const float*)d_in[3];
    const float* f_s_b  = (const float*)d_in[4];
    const float* f_m_w  = (const float*)d_in[5];
    const float* f_m_b  = (const float*)d_in[6];
    const float* Wq1    = (const float*)d_in[7];
    const float* Wk1    = (const float*)d_in[8];
    const float* Wq2    = (const float*)d_in[9];
    const float* Wk2    = (const float*)d_in[10];
    const float* Wv     = (const float*)d_in[11];
    const float* proj_w = (const float*)d_in[12];
    const float* proj_b = (const float*)d_in[13];
    const float* gs_w   = (const float*)d_in[14];
    const float* gs_b   = (const float*)d_in[15];

    static cudaStream_t s1 = nullptr, s2 = nullptr;
    static cudaEvent_t evr = nullptr, ev1 = nullptr, ev2 = nullptr;
    if (!s1) {
        cudaStreamCreateWithFlags(&s1, cudaStreamNonBlocking);
        cudaStreamCreateWithFlags(&s2, cudaStreamNonBlocking);
        cudaEventCreateWithFlags(&evr, cudaEventDisableTiming);
        cudaEventCreateWithFlags(&ev1, cudaEventDisableTiming);
        cudaEventCreateWithFlags(&ev2, cudaEventDisableTiming);
        cudaFuncSetAttribute(projZ_kernel, cudaFuncAttributeMaxDynamicSharedMemorySize,
                             (BB * (NM + 1) + 16) * 4);
    }

    float *p_csp, *p_q1, *p_qk1, *p_cmp, *p_q2, *p_qk2, *p_part1, *p_part2;
    cudaGetSymbolAddress((void**)&p_csp,   g_csp);
    cudaGetSymbolAddress((void**)&p_q1,    g_q1);
    cudaGetSymbolAddress((void**)&p_qk1,   g_qk1);
    cudaGetSymbolAddress((void**)&p_cmp,   g_cmp);
    cudaGetSymbolAddress((void**)&p_q2,    g_q2);
    cudaGetSymbolAddress((void**)&p_qk2,   g_qk2);
    cudaGetSymbolAddress((void**)&p_part1, g_part1);
    cudaGetSymbolAddress((void**)&p_part2, g_part2);

    // fork
    cudaEventRecord(evr, 0);
    cudaStreamWaitEvent(s1, evr, 0);
    cudaStreamWaitEvent(s2, evr, 0);

    // Branch 1 (att1 chain): csp -> q1 -> qk1 -> score1e -> projZ
    gemvA_kernel<<<64, 256, 0, s1>>>(f_s_w, x2, (NL * DS) / 4, f_s_b, p_csp, DM, DS);
    gemvA_kernel<<<64, 256, 0, s1>>>(Wq1, p_csp, DM / 4, nullptr, p_q1, DM, DM);
    gemvB_kernel<<<dim3(2, MCH), 256, 0, s1>>>(Wk1, p_q1, p_part1, DM, DM);
    gemvBred_kernel<<<32, 256, 0, s1>>>(p_part1, p_qk1, DM);
    score1e_kernel<<<514, 256, 0, s1>>>(x1);
    projZ_kernel<<<(NKV + 7) / 8, 256, (BB * (NM + 1) + 16) * 4, s1>>>(proj_w, proj_b);

    // Branch 2 (qk2 chain): cmp -> q2 -> qk2
    gemvA_kernel<<<128, 256, 0, s2>>>(f_m_w, x1, ((NM + 1) * DM) / 4, f_m_b, p_cmp, DL, DM);
    gemvA_kernel<<<128, 256, 0, s2>>>(Wq2, p_cmp, DL / 4, nullptr, p_q2, DL, DL);
    gemvB_kernel<<<dim3(4, MCH), 256, 0, s2>>>(Wk2, p_q2, p_part2, DL, DL);
    gemvBred_kernel<<<64, 256, 0, s2>>>(p_part2, p_qk2, DL);

    // join
    cudaEventRecord(ev1, s1);
    cudaEventRecord(ev2, s2);
    cudaStreamWaitEvent(0, ev1, 0);
    cudaStreamWaitEvent(0, ev2, 0);

    // main chain
    big_kernel<<<dim3(NCHUNK, BB), 256>>>(x0);
    tail_kernel<<<TGRID, 256>>>(x0, Wv, gs_w, gs_b, (float*)d_out);
}